// round 13
// baseline (speedup 1.0000x reference)
#include <cuda_runtime.h>
#include <math.h>

// Problem constants (fixed by the dataset)
#define BTOT 131072
#define INF  128
#define HH   256
#define KCH  32     // K chunk per smem stage
#define SMS  36     // smem row stride in floats: (r*36+c)%32 == (r*4+c)%32 -> conflict-free frags

// Scratch for p = relu(x@Wp^T + bp): 131072*256 fp32 = 134 MB (device global, no alloc)
static __device__ float g_P[(size_t)BTOT * (size_t)HH];

__device__ __forceinline__ unsigned f2tf(float x) {
    unsigned r;
    asm("cvt.rna.tf32.f32 %0, %1;" : "=r"(r) : "f"(x));
    return r;
}

// D += A(16x8,row) * B(8x8,col) in tf32 with fp32 accumulate
__device__ __forceinline__ void mma8(float d[4], const unsigned a[4], const unsigned b[2]) {
    asm volatile(
        "mma.sync.aligned.m16n8k8.row.col.f32.tf32.tf32.f32 "
        "{%0,%1,%2,%3}, {%4,%5,%6,%7}, {%8,%9}, {%0,%1,%2,%3};\n"
        : "+f"(d[0]), "+f"(d[1]), "+f"(d[2]), "+f"(d[3])
        : "r"(a[0]), "r"(a[1]), "r"(a[2]), "r"(a[3]), "r"(b[0]), "r"(b[1]));
}

// ---------------------------------------------------------------------------
// Kernel 1: P[B,256] = relu(X[B,128] @ Wp^T + bp)   (unchanged from R8 pass)
// ---------------------------------------------------------------------------
__global__ __launch_bounds__(256) void proj_kernel(
    const float* __restrict__ X,
    const float* __restrict__ Wp,
    const float* __restrict__ bp)
{
    __shared__ unsigned Xs[128 * SMS];
    __shared__ unsigned Ws[64 * SMS];

    const int tid  = threadIdx.x;
    const int lane = tid & 31;
    const int warp = tid >> 5;
    const int g    = lane >> 2;
    const int tg   = lane & 3;
    const int wm   = warp >> 1;
    const int wn   = warp & 1;
    const int m0   = blockIdx.y * 128;
    const int n0   = blockIdx.x * 64;

    float acc[2][4][4];
    #pragma unroll
    for (int i = 0; i < 2; i++)
        #pragma unroll
        for (int j = 0; j < 4; j++)
            #pragma unroll
            for (int q = 0; q < 4; q++) acc[i][j][q] = 0.f;

    for (int kc = 0; kc < INF; kc += KCH) {
        #pragma unroll
        for (int i = 0; i < 4; i++) {
            int s   = tid + i * 256;
            int row = s >> 3;
            int c4  = (s & 7) << 2;
            float4 v = *(const float4*)&X[(size_t)(m0 + row) * INF + kc + c4];
            unsigned* p = &Xs[row * SMS + c4];
            p[0] = f2tf(v.x); p[1] = f2tf(v.y); p[2] = f2tf(v.z); p[3] = f2tf(v.w);
        }
        #pragma unroll
        for (int i = 0; i < 2; i++) {
            int s   = tid + i * 256;
            int row = s >> 3;
            int c4  = (s & 7) << 2;
            float4 v = *(const float4*)&Wp[(size_t)(n0 + row) * INF + kc + c4];
            unsigned* p = &Ws[row * SMS + c4];
            p[0] = f2tf(v.x); p[1] = f2tf(v.y); p[2] = f2tf(v.z); p[3] = f2tf(v.w);
        }
        __syncthreads();

        #pragma unroll
        for (int ks = 0; ks < KCH; ks += 8) {
            unsigned a[2][4];
            #pragma unroll
            for (int fm = 0; fm < 2; fm++) {
                int r = wm * 32 + fm * 16 + g;
                const unsigned* base = &Xs[r * SMS + ks + tg];
                a[fm][0] = base[0];
                a[fm][1] = base[8 * SMS];
                a[fm][2] = base[4];
                a[fm][3] = base[8 * SMS + 4];
            }
            #pragma unroll
            for (int fn = 0; fn < 4; fn++) {
                int nr = wn * 32 + fn * 8 + g;
                unsigned b[2];
                b[0] = Ws[nr * SMS + ks + tg];
                b[1] = Ws[nr * SMS + ks + tg + 4];
                #pragma unroll
                for (int fm = 0; fm < 2; fm++) mma8(acc[fm][fn], a[fm], b);
            }
        }
        __syncthreads();
    }

    #pragma unroll
    for (int fm = 0; fm < 2; fm++) {
        #pragma unroll
        for (int fn = 0; fn < 4; fn++) {
            int r0 = m0 + wm * 32 + fm * 16 + g;
            int c0 = n0 + wn * 32 + fn * 8 + tg * 2;
            float b0 = bp[c0], b1 = bp[c0 + 1];
            g_P[(size_t)r0 * HH + c0]           = fmaxf(acc[fm][fn][0] + b0, 0.f);
            g_P[(size_t)r0 * HH + c0 + 1]       = fmaxf(acc[fm][fn][1] + b1, 0.f);
            g_P[(size_t)(r0 + 8) * HH + c0]     = fmaxf(acc[fm][fn][2] + b0, 0.f);
            g_P[(size_t)(r0 + 8) * HH + c0 + 1] = fmaxf(acc[fm][fn][3] + b1, 0.f);
        }
    }
}

// ---------------------------------------------------------------------------
// Kernel 2: fused GRU cell — big warp tiles + register-staged pipeline.
// CTA: 256 thr, 8 warps = 2(m) x 4(n). Warp tile 64 rows x 16 j (48 gate cols).
// CTA tile: 128 rows x 64 j. Accumulators: 4fm x 2fn x {ar,az,ain,ahn} = 128 regs.
// Phase 0: A=h0, W=W_hh (-> ar, az, hn). Phase 1: A=P, W=W_ih (-> ar, az, in).
// ---------------------------------------------------------------------------
__global__ __launch_bounds__(256) void gru_kernel(
    const float* __restrict__ H0,
    const float* __restrict__ Wih,
    const float* __restrict__ Whh,
    const float* __restrict__ bih,
    const float* __restrict__ bhh,
    float* __restrict__ out)
{
    __shared__ unsigned As[128 * SMS];   // A chunk: 128 rows x 32 k
    __shared__ unsigned Ws[192 * SMS];   // W chunk: rows = gate*64 + jj (jj<64), 32 k

    const int tid  = threadIdx.x;
    const int lane = tid & 31;
    const int warp = tid >> 5;
    const int g    = lane >> 2;
    const int tg   = lane & 3;
    const int wm   = warp >> 2;   // 0..1 -> 64 rows each
    const int wn   = warp & 3;    // 0..3 -> 16 j each
    const int m0   = blockIdx.y * 128;
    const int j0   = blockIdx.x * 64;

    // ---- staging geometry (constant per thread) ----
    const int rbase = tid >> 3;         // 0..31
    const int c4    = (tid & 7) << 2;   // 0,4,..,28
    int wrow[6];                         // global W row for each of 6 staged float4s
    #pragma unroll
    for (int i = 0; i < 6; i++) {
        int row = rbase + 32 * i;        // Ws row 0..191
        wrow[i] = (row >> 6) * HH + j0 + (row & 63);
    }

    float ar[4][2][4], az[4][2][4], ain[4][2][4], ahn[4][2][4];
    #pragma unroll
    for (int i = 0; i < 4; i++)
        #pragma unroll
        for (int j = 0; j < 2; j++)
            #pragma unroll
            for (int q = 0; q < 4; q++) {
                ar[i][j][q] = 0.f; az[i][j][q] = 0.f;
                ain[i][j][q] = 0.f; ahn[i][j][q] = 0.f;
            }

    float4 sa[4], sw[6];

    // prologue: stage chunk 0 (phase 0: A=H0, W=Whh, kc=0)
    #pragma unroll
    for (int i = 0; i < 4; i++)
        sa[i] = *(const float4*)&H0[(size_t)(m0 + rbase + 32 * i) * HH + c4];
    #pragma unroll
    for (int i = 0; i < 6; i++)
        sw[i] = *(const float4*)&Whh[(size_t)wrow[i] * HH + c4];

    #pragma unroll
    for (int ph = 0; ph < 2; ph++) {
        for (int kci = 0; kci < 8; kci++) {
            // ---- store staged chunk to smem (with tf32 round) ----
            #pragma unroll
            for (int i = 0; i < 4; i++) {
                unsigned* p = &As[(rbase + 32 * i) * SMS + c4];
                p[0] = f2tf(sa[i].x); p[1] = f2tf(sa[i].y);
                p[2] = f2tf(sa[i].z); p[3] = f2tf(sa[i].w);
            }
            #pragma unroll
            for (int i = 0; i < 6; i++) {
                unsigned* p = &Ws[(rbase + 32 * i) * SMS + c4];
                p[0] = f2tf(sw[i].x); p[1] = f2tf(sw[i].y);
                p[2] = f2tf(sw[i].z); p[3] = f2tf(sw[i].w);
            }
            __syncthreads();

            // ---- stage next chunk (hides gmem latency under MMAs) ----
            int c = ph * 8 + kci;
            if (c < 15) {
                int cn  = c + 1;
                int kcn = (cn & 7) * KCH;
                const float* An = (cn >> 3) ? (const float*)g_P : H0;
                const float* Wn = (cn >> 3) ? Wih : Whh;
                #pragma unroll
                for (int i = 0; i < 4; i++)
                    sa[i] = *(const float4*)&An[(size_t)(m0 + rbase + 32 * i) * HH + kcn + c4];
                #pragma unroll
                for (int i = 0; i < 6; i++)
                    sw[i] = *(const float4*)&Wn[(size_t)wrow[i] * HH + kcn + c4];
            }

            // ---- MMAs over current chunk ----
            #pragma unroll
            for (int ks = 0; ks < KCH; ks += 8) {
                unsigned a[4][4];
                #pragma unroll
                for (int fm = 0; fm < 4; fm++) {
                    int r = wm * 64 + fm * 16 + g;
                    const unsigned* base = &As[r * SMS + ks + tg];
                    a[fm][0] = base[0];
                    a[fm][1] = base[8 * SMS];
                    a[fm][2] = base[4];
                    a[fm][3] = base[8 * SMS + 4];
                }
                #pragma unroll
                for (int gate = 0; gate < 3; gate++) {
                    #pragma unroll
                    for (int fn = 0; fn < 2; fn++) {
                        int nr = gate * 64 + wn * 16 + fn * 8 + g;
                        unsigned b[2];
                        b[0] = Ws[nr * SMS + ks + tg];
                        b[1] = Ws[nr * SMS + ks + tg + 4];
                        #pragma unroll
                        for (int fm = 0; fm < 4; fm++) {
                            float* acc = (gate == 0) ? ar[fm][fn]
                                       : (gate == 1) ? az[fm][fn]
                                       : ((ph == 0) ? ahn[fm][fn] : ain[fm][fn]);
                            mma8(acc, a[fm], b);
                        }
                    }
                }
            }
            __syncthreads();
        }
    }

    // ---- Epilogue: biases, gates, blend, write both output copies (float2) ----
    const size_t BH = (size_t)BTOT * (size_t)HH;
    #pragma unroll
    for (int fn = 0; fn < 2; fn++) {
        int jb = j0 + wn * 16 + fn * 8 + tg * 2;
        float br0 = bih[jb]              + bhh[jb];
        float br1 = bih[jb + 1]          + bhh[jb + 1];
        float bz0 = bih[HH + jb]         + bhh[HH + jb];
        float bz1 = bih[HH + jb + 1]     + bhh[HH + jb + 1];
        float bi0 = bih[2 * HH + jb];
        float bi1 = bih[2 * HH + jb + 1];
        float bh0 = bhh[2 * HH + jb];
        float bh1 = bhh[2 * HH + jb + 1];
        #pragma unroll
        for (int fm = 0; fm < 4; fm++) {
            int r0 = m0 + wm * 64 + fm * 16 + g;
            #pragma unroll
            for (int half = 0; half < 2; half++) {
                int row = r0 + half * 8;
                int q0 = half * 2;
                float2 h0v = *(const float2*)&H0[(size_t)row * HH + jb];
                float vr0 = ar[fm][fn][q0]      + br0;
                float vr1 = ar[fm][fn][q0 + 1]  + br1;
                float vz0 = az[fm][fn][q0]      + bz0;
                float vz1 = az[fm][fn][q0 + 1]  + bz1;
                float vi0 = ain[fm][fn][q0]     + bi0;
                float vi1 = ain[fm][fn][q0 + 1] + bi1;
                float vh0 = ahn[fm][fn][q0]     + bh0;
                float vh1 = ahn[fm][fn][q0 + 1] + bh1;
                float rr0 = 1.f / (1.f + __expf(-vr0));
                float rr1 = 1.f / (1.f + __expf(-vr1));
                float zz0 = 1.f / (1.f + __expf(-vz0));
                float zz1 = 1.f / (1.f + __expf(-vz1));
                float nn0 = tanhf(vi0 + rr0 * vh0);
                float nn1 = tanhf(vi1 + rr1 * vh1);
                float2 nh;
                nh.x = fmaf(zz0, h0v.x - nn0, nn0);
                nh.y = fmaf(zz1, h0v.y - nn1, nn1);
                size_t idx = (size_t)row * HH + jb;
                *(float2*)&out[idx]      = nh;
                *(float2*)&out[BH + idx] = nh;
            }
        }
    }
}

// ---------------------------------------------------------------------------
// kernel_launch: inputs in metadata order x, h, Wp, bp, W_ih, W_hh, b_ih, b_hh
// ---------------------------------------------------------------------------
extern "C" void kernel_launch(void* const* d_in, const int* in_sizes, int n_in,
                              void* d_out, int out_size) {
    const float* x   = (const float*)d_in[0];
    const float* h   = (const float*)d_in[1];   // (1, B, H) contiguous == (B, H)
    const float* Wp  = (const float*)d_in[2];
    const float* bp  = (const float*)d_in[3];
    const float* Wih = (const float*)d_in[4];
    const float* Whh = (const float*)d_in[5];
    const float* bih = (const float*)d_in[6];
    const float* bhh = (const float*)d_in[7];
    float* out = (float*)d_out;

    dim3 gA(HH / 64, BTOT / 128);   // (4, 1024)
    proj_kernel<<<gA, 256>>>(x, Wp, bp);

    dim3 gB(HH / 64, BTOT / 128);   // (4, 1024) — j fastest for L2 reuse of h/P tiles
    gru_kernel<<<gB, 256>>>(h, Wih, Whh, bih, bhh, out);
}

// round 14
// speedup vs baseline: 1.0008x; 1.0008x over previous
#include <cuda_runtime.h>
#include <math.h>

// Problem constants (fixed by the dataset)
#define BTOT 131072
#define INF  128
#define HH   256
#define KCH  32     // K chunk per smem stage
#define SMS  36     // smem row stride in floats: (r*36+c)%32 == (r*4+c)%32 -> conflict-free frags

// Scratch for p = relu(x@Wp^T + bp): 131072*256 fp32 = 134 MB (device global, no alloc)
static __device__ float g_P[(size_t)BTOT * (size_t)HH];

__device__ __forceinline__ unsigned f2tf(float x) {
    unsigned r;
    asm("cvt.rna.tf32.f32 %0, %1;" : "=r"(r) : "f"(x));
    return r;
}

// D += A(16x8,row) * B(8x8,col) in tf32 with fp32 accumulate
__device__ __forceinline__ void mma8(float d[4], const unsigned a[4], const unsigned b[2]) {
    asm volatile(
        "mma.sync.aligned.m16n8k8.row.col.f32.tf32.tf32.f32 "
        "{%0,%1,%2,%3}, {%4,%5,%6,%7}, {%8,%9}, {%0,%1,%2,%3};\n"
        : "+f"(d[0]), "+f"(d[1]), "+f"(d[2]), "+f"(d[3])
        : "r"(a[0]), "r"(a[1]), "r"(a[2]), "r"(a[3]), "r"(b[0]), "r"(b[1]));
}

// ---------------------------------------------------------------------------
// Kernel 1: P[B,256] = relu(X[B,128] @ Wp^T + bp)   (unchanged from R8 pass)
// ---------------------------------------------------------------------------
__global__ __launch_bounds__(256) void proj_kernel(
    const float* __restrict__ X,
    const float* __restrict__ Wp,
    const float* __restrict__ bp)
{
    __shared__ unsigned Xs[128 * SMS];
    __shared__ unsigned Ws[64 * SMS];

    const int tid  = threadIdx.x;
    const int lane = tid & 31;
    const int warp = tid >> 5;
    const int g    = lane >> 2;
    const int tg   = lane & 3;
    const int wm   = warp >> 1;
    const int wn   = warp & 1;
    const int m0   = blockIdx.y * 128;
    const int n0   = blockIdx.x * 64;

    float acc[2][4][4];
    #pragma unroll
    for (int i = 0; i < 2; i++)
        #pragma unroll
        for (int j = 0; j < 4; j++)
            #pragma unroll
            for (int q = 0; q < 4; q++) acc[i][j][q] = 0.f;

    for (int kc = 0; kc < INF; kc += KCH) {
        #pragma unroll
        for (int i = 0; i < 4; i++) {
            int s   = tid + i * 256;
            int row = s >> 3;
            int c4  = (s & 7) << 2;
            float4 v = *(const float4*)&X[(size_t)(m0 + row) * INF + kc + c4];
            unsigned* p = &Xs[row * SMS + c4];
            p[0] = f2tf(v.x); p[1] = f2tf(v.y); p[2] = f2tf(v.z); p[3] = f2tf(v.w);
        }
        #pragma unroll
        for (int i = 0; i < 2; i++) {
            int s   = tid + i * 256;
            int row = s >> 3;
            int c4  = (s & 7) << 2;
            float4 v = *(const float4*)&Wp[(size_t)(n0 + row) * INF + kc + c4];
            unsigned* p = &Ws[row * SMS + c4];
            p[0] = f2tf(v.x); p[1] = f2tf(v.y); p[2] = f2tf(v.z); p[3] = f2tf(v.w);
        }
        __syncthreads();

        #pragma unroll
        for (int ks = 0; ks < KCH; ks += 8) {
            unsigned a[2][4];
            #pragma unroll
            for (int fm = 0; fm < 2; fm++) {
                int r = wm * 32 + fm * 16 + g;
                const unsigned* base = &Xs[r * SMS + ks + tg];
                a[fm][0] = base[0];
                a[fm][1] = base[8 * SMS];
                a[fm][2] = base[4];
                a[fm][3] = base[8 * SMS + 4];
            }
            #pragma unroll
            for (int fn = 0; fn < 4; fn++) {
                int nr = wn * 32 + fn * 8 + g;
                unsigned b[2];
                b[0] = Ws[nr * SMS + ks + tg];
                b[1] = Ws[nr * SMS + ks + tg + 4];
                #pragma unroll
                for (int fm = 0; fm < 2; fm++) mma8(acc[fm][fn], a[fm], b);
            }
        }
        __syncthreads();
    }

    #pragma unroll
    for (int fm = 0; fm < 2; fm++) {
        #pragma unroll
        for (int fn = 0; fn < 4; fn++) {
            int r0 = m0 + wm * 32 + fm * 16 + g;
            int c0 = n0 + wn * 32 + fn * 8 + tg * 2;
            float b0 = bp[c0], b1 = bp[c0 + 1];
            g_P[(size_t)r0 * HH + c0]           = fmaxf(acc[fm][fn][0] + b0, 0.f);
            g_P[(size_t)r0 * HH + c0 + 1]       = fmaxf(acc[fm][fn][1] + b1, 0.f);
            g_P[(size_t)(r0 + 8) * HH + c0]     = fmaxf(acc[fm][fn][2] + b0, 0.f);
            g_P[(size_t)(r0 + 8) * HH + c0 + 1] = fmaxf(acc[fm][fn][3] + b1, 0.f);
        }
    }
}

// ---------------------------------------------------------------------------
// Kernel 2: fused GRU cell — big warp tiles + register-staged pipeline.
// CTA: 256 thr, 8 warps = 2(m) x 4(n). Warp tile 64 rows x 16 j (48 gate cols).
// CTA tile: 128 rows x 64 j. Accumulators: 4fm x 2fn x {ar,az,ain,ahn} = 128 regs.
// Phase 0: A=h0, W=W_hh (-> ar, az, hn). Phase 1: A=P, W=W_ih (-> ar, az, in).
// ---------------------------------------------------------------------------
__global__ __launch_bounds__(256) void gru_kernel(
    const float* __restrict__ H0,
    const float* __restrict__ Wih,
    const float* __restrict__ Whh,
    const float* __restrict__ bih,
    const float* __restrict__ bhh,
    float* __restrict__ out)
{
    __shared__ unsigned As[128 * SMS];   // A chunk: 128 rows x 32 k
    __shared__ unsigned Ws[192 * SMS];   // W chunk: rows = gate*64 + jj (jj<64), 32 k

    const int tid  = threadIdx.x;
    const int lane = tid & 31;
    const int warp = tid >> 5;
    const int g    = lane >> 2;
    const int tg   = lane & 3;
    const int wm   = warp >> 2;   // 0..1 -> 64 rows each
    const int wn   = warp & 3;    // 0..3 -> 16 j each
    const int m0   = blockIdx.y * 128;
    const int j0   = blockIdx.x * 64;

    // ---- staging geometry (constant per thread) ----
    const int rbase = tid >> 3;         // 0..31
    const int c4    = (tid & 7) << 2;   // 0,4,..,28
    int wrow[6];                         // global W row for each of 6 staged float4s
    #pragma unroll
    for (int i = 0; i < 6; i++) {
        int row = rbase + 32 * i;        // Ws row 0..191
        wrow[i] = (row >> 6) * HH + j0 + (row & 63);
    }

    float ar[4][2][4], az[4][2][4], ain[4][2][4], ahn[4][2][4];
    #pragma unroll
    for (int i = 0; i < 4; i++)
        #pragma unroll
        for (int j = 0; j < 2; j++)
            #pragma unroll
            for (int q = 0; q < 4; q++) {
                ar[i][j][q] = 0.f; az[i][j][q] = 0.f;
                ain[i][j][q] = 0.f; ahn[i][j][q] = 0.f;
            }

    float4 sa[4], sw[6];

    // prologue: stage chunk 0 (phase 0: A=H0, W=Whh, kc=0)
    #pragma unroll
    for (int i = 0; i < 4; i++)
        sa[i] = *(const float4*)&H0[(size_t)(m0 + rbase + 32 * i) * HH + c4];
    #pragma unroll
    for (int i = 0; i < 6; i++)
        sw[i] = *(const float4*)&Whh[(size_t)wrow[i] * HH + c4];

    #pragma unroll
    for (int ph = 0; ph < 2; ph++) {
        for (int kci = 0; kci < 8; kci++) {
            // ---- store staged chunk to smem (with tf32 round) ----
            #pragma unroll
            for (int i = 0; i < 4; i++) {
                unsigned* p = &As[(rbase + 32 * i) * SMS + c4];
                p[0] = f2tf(sa[i].x); p[1] = f2tf(sa[i].y);
                p[2] = f2tf(sa[i].z); p[3] = f2tf(sa[i].w);
            }
            #pragma unroll
            for (int i = 0; i < 6; i++) {
                unsigned* p = &Ws[(rbase + 32 * i) * SMS + c4];
                p[0] = f2tf(sw[i].x); p[1] = f2tf(sw[i].y);
                p[2] = f2tf(sw[i].z); p[3] = f2tf(sw[i].w);
            }
            __syncthreads();

            // ---- stage next chunk (hides gmem latency under MMAs) ----
            int c = ph * 8 + kci;
            if (c < 15) {
                int cn  = c + 1;
                int kcn = (cn & 7) * KCH;
                const float* An = (cn >> 3) ? (const float*)g_P : H0;
                const float* Wn = (cn >> 3) ? Wih : Whh;
                #pragma unroll
                for (int i = 0; i < 4; i++)
                    sa[i] = *(const float4*)&An[(size_t)(m0 + rbase + 32 * i) * HH + kcn + c4];
                #pragma unroll
                for (int i = 0; i < 6; i++)
                    sw[i] = *(const float4*)&Wn[(size_t)wrow[i] * HH + kcn + c4];
            }

            // ---- MMAs over current chunk ----
            #pragma unroll
            for (int ks = 0; ks < KCH; ks += 8) {
                unsigned a[4][4];
                #pragma unroll
                for (int fm = 0; fm < 4; fm++) {
                    int r = wm * 64 + fm * 16 + g;
                    const unsigned* base = &As[r * SMS + ks + tg];
                    a[fm][0] = base[0];
                    a[fm][1] = base[8 * SMS];
                    a[fm][2] = base[4];
                    a[fm][3] = base[8 * SMS + 4];
                }
                #pragma unroll
                for (int gate = 0; gate < 3; gate++) {
                    #pragma unroll
                    for (int fn = 0; fn < 2; fn++) {
                        int nr = gate * 64 + wn * 16 + fn * 8 + g;
                        unsigned b[2];
                        b[0] = Ws[nr * SMS + ks + tg];
                        b[1] = Ws[nr * SMS + ks + tg + 4];
                        #pragma unroll
                        for (int fm = 0; fm < 4; fm++) {
                            float* acc = (gate == 0) ? ar[fm][fn]
                                       : (gate == 1) ? az[fm][fn]
                                       : ((ph == 0) ? ahn[fm][fn] : ain[fm][fn]);
                            mma8(acc, a[fm], b);
                        }
                    }
                }
            }
            __syncthreads();
        }
    }

    // ---- Epilogue: biases, gates, blend, write both output copies (float2) ----
    const size_t BH = (size_t)BTOT * (size_t)HH;
    #pragma unroll
    for (int fn = 0; fn < 2; fn++) {
        int jb = j0 + wn * 16 + fn * 8 + tg * 2;
        float br0 = bih[jb]              + bhh[jb];
        float br1 = bih[jb + 1]          + bhh[jb + 1];
        float bz0 = bih[HH + jb]         + bhh[HH + jb];
        float bz1 = bih[HH + jb + 1]     + bhh[HH + jb + 1];
        float bi0 = bih[2 * HH + jb];
        float bi1 = bih[2 * HH + jb + 1];
        float bh0 = bhh[2 * HH + jb];
        float bh1 = bhh[2 * HH + jb + 1];
        #pragma unroll
        for (int fm = 0; fm < 4; fm++) {
            int r0 = m0 + wm * 64 + fm * 16 + g;
            #pragma unroll
            for (int half = 0; half < 2; half++) {
                int row = r0 + half * 8;
                int q0 = half * 2;
                float2 h0v = *(const float2*)&H0[(size_t)row * HH + jb];
                float vr0 = ar[fm][fn][q0]      + br0;
                float vr1 = ar[fm][fn][q0 + 1]  + br1;
                float vz0 = az[fm][fn][q0]      + bz0;
                float vz1 = az[fm][fn][q0 + 1]  + bz1;
                float vi0 = ain[fm][fn][q0]     + bi0;
                float vi1 = ain[fm][fn][q0 + 1] + bi1;
                float vh0 = ahn[fm][fn][q0]     + bh0;
                float vh1 = ahn[fm][fn][q0 + 1] + bh1;
                float rr0 = 1.f / (1.f + __expf(-vr0));
                float rr1 = 1.f / (1.f + __expf(-vr1));
                float zz0 = 1.f / (1.f + __expf(-vz0));
                float zz1 = 1.f / (1.f + __expf(-vz1));
                float nn0 = tanhf(vi0 + rr0 * vh0);
                float nn1 = tanhf(vi1 + rr1 * vh1);
                float2 nh;
                nh.x = fmaf(zz0, h0v.x - nn0, nn0);
                nh.y = fmaf(zz1, h0v.y - nn1, nn1);
                size_t idx = (size_t)row * HH + jb;
                *(float2*)&out[idx]      = nh;
                *(float2*)&out[BH + idx] = nh;
            }
        }
    }
}

// ---------------------------------------------------------------------------
// kernel_launch: inputs in metadata order x, h, Wp, bp, W_ih, W_hh, b_ih, b_hh
// ---------------------------------------------------------------------------
extern "C" void kernel_launch(void* const* d_in, const int* in_sizes, int n_in,
                              void* d_out, int out_size) {
    const float* x   = (const float*)d_in[0];
    const float* h   = (const float*)d_in[1];   // (1, B, H) contiguous == (B, H)
    const float* Wp  = (const float*)d_in[2];
    const float* bp  = (const float*)d_in[3];
    const float* Wih = (const float*)d_in[4];
    const float* Whh = (const float*)d_in[5];
    const float* bih = (const float*)d_in[6];
    const float* bhh = (const float*)d_in[7];
    float* out = (float*)d_out;

    dim3 gA(HH / 64, BTOT / 128);   // (4, 1024)
    proj_kernel<<<gA, 256>>>(x, Wp, bp);

    dim3 gB(HH / 64, BTOT / 128);   // (4, 1024) — j fastest for L2 reuse of h/P tiles
    gru_kernel<<<gB, 256>>>(h, Wih, Whh, bih, bhh, out);
}

// round 15
// speedup vs baseline: 1.2133x; 1.2124x over previous
#include <cuda_runtime.h>
#include <math.h>

// Problem constants (fixed by the dataset)
#define BTOT 131072
#define INF  128
#define HH   256
#define KCH  32     // K chunk per smem stage
#define SMS  36     // smem row stride in floats: (r*36+c)%32 == (r*4+c)%32 -> conflict-free frags

// tf32-rounded scratch: P = relu(x@Wp^T+bp) (134 MB) and pre-rounded GRU weights
static __device__ unsigned g_P[(size_t)BTOT * (size_t)HH];
static __device__ unsigned g_Wih_t[3 * HH * HH];
static __device__ unsigned g_Whh_t[3 * HH * HH];

__device__ __forceinline__ unsigned f2tf(float x) {
    unsigned r;
    asm("cvt.rna.tf32.f32 %0, %1;" : "=r"(r) : "f"(x));
    return r;
}

// D += A(16x8,row) * B(8x8,col) in tf32 with fp32 accumulate
__device__ __forceinline__ void mma8(float d[4], const unsigned a[4], const unsigned b[2]) {
    asm volatile(
        "mma.sync.aligned.m16n8k8.row.col.f32.tf32.tf32.f32 "
        "{%0,%1,%2,%3}, {%4,%5,%6,%7}, {%8,%9}, {%0,%1,%2,%3};\n"
        : "+f"(d[0]), "+f"(d[1]), "+f"(d[2]), "+f"(d[3])
        : "r"(a[0]), "r"(a[1]), "r"(a[2]), "r"(a[3]), "r"(b[0]), "r"(b[1]));
}

__device__ __forceinline__ void cpa16(unsigned saddr, const void* gaddr) {
    asm volatile("cp.async.cg.shared.global [%0], [%1], 16;"
                 :: "r"(saddr), "l"(gaddr) : "memory");
}

// ---------------------------------------------------------------------------
// Kernel 0: pre-round GRU weights to tf32 bits (runs once per launch, ~2us)
// ---------------------------------------------------------------------------
__global__ __launch_bounds__(256) void wprep_kernel(
    const float* __restrict__ Wih, const float* __restrict__ Whh)
{
    int i = blockIdx.x * 256 + threadIdx.x;   // 3*256*256 = 196608 total
    g_Wih_t[i] = f2tf(Wih[i]);
    g_Whh_t[i] = f2tf(Whh[i]);
}

// ---------------------------------------------------------------------------
// Kernel 1: P[B,256] = relu(X[B,128] @ Wp^T + bp), stored as tf32 bits.
// ---------------------------------------------------------------------------
__global__ __launch_bounds__(256) void proj_kernel(
    const float* __restrict__ X,
    const float* __restrict__ Wp,
    const float* __restrict__ bp)
{
    __shared__ unsigned Xs[128 * SMS];
    __shared__ unsigned Ws[64 * SMS];

    const int tid  = threadIdx.x;
    const int lane = tid & 31;
    const int warp = tid >> 5;
    const int g    = lane >> 2;
    const int tg   = lane & 3;
    const int wm   = warp >> 1;
    const int wn   = warp & 1;
    const int m0   = blockIdx.y * 128;
    const int n0   = blockIdx.x * 64;

    float acc[2][4][4];
    #pragma unroll
    for (int i = 0; i < 2; i++)
        #pragma unroll
        for (int j = 0; j < 4; j++)
            #pragma unroll
            for (int q = 0; q < 4; q++) acc[i][j][q] = 0.f;

    for (int kc = 0; kc < INF; kc += KCH) {
        #pragma unroll
        for (int i = 0; i < 4; i++) {
            int s   = tid + i * 256;
            int row = s >> 3;
            int c4  = (s & 7) << 2;
            float4 v = *(const float4*)&X[(size_t)(m0 + row) * INF + kc + c4];
            unsigned* p = &Xs[row * SMS + c4];
            p[0] = f2tf(v.x); p[1] = f2tf(v.y); p[2] = f2tf(v.z); p[3] = f2tf(v.w);
        }
        #pragma unroll
        for (int i = 0; i < 2; i++) {
            int s   = tid + i * 256;
            int row = s >> 3;
            int c4  = (s & 7) << 2;
            float4 v = *(const float4*)&Wp[(size_t)(n0 + row) * INF + kc + c4];
            unsigned* p = &Ws[row * SMS + c4];
            p[0] = f2tf(v.x); p[1] = f2tf(v.y); p[2] = f2tf(v.z); p[3] = f2tf(v.w);
        }
        __syncthreads();

        #pragma unroll
        for (int ks = 0; ks < KCH; ks += 8) {
            unsigned a[2][4];
            #pragma unroll
            for (int fm = 0; fm < 2; fm++) {
                int r = wm * 32 + fm * 16 + g;
                const unsigned* base = &Xs[r * SMS + ks + tg];
                a[fm][0] = base[0];
                a[fm][1] = base[8 * SMS];
                a[fm][2] = base[4];
                a[fm][3] = base[8 * SMS + 4];
            }
            #pragma unroll
            for (int fn = 0; fn < 4; fn++) {
                int nr = wn * 32 + fn * 8 + g;
                unsigned b[2];
                b[0] = Ws[nr * SMS + ks + tg];
                b[1] = Ws[nr * SMS + ks + tg + 4];
                #pragma unroll
                for (int fm = 0; fm < 2; fm++) mma8(acc[fm][fn], a[fm], b);
            }
        }
        __syncthreads();
    }

    // epilogue: +bias, relu, store tf32 bits to g_P
    #pragma unroll
    for (int fm = 0; fm < 2; fm++) {
        #pragma unroll
        for (int fn = 0; fn < 4; fn++) {
            int r0 = m0 + wm * 32 + fm * 16 + g;
            int c0 = n0 + wn * 32 + fn * 8 + tg * 2;
            float b0 = bp[c0], b1 = bp[c0 + 1];
            g_P[(size_t)r0 * HH + c0]           = f2tf(fmaxf(acc[fm][fn][0] + b0, 0.f));
            g_P[(size_t)r0 * HH + c0 + 1]       = f2tf(fmaxf(acc[fm][fn][1] + b1, 0.f));
            g_P[(size_t)(r0 + 8) * HH + c0]     = f2tf(fmaxf(acc[fm][fn][2] + b0, 0.f));
            g_P[(size_t)(r0 + 8) * HH + c0 + 1] = f2tf(fmaxf(acc[fm][fn][3] + b1, 0.f));
        }
    }
}

// ---------------------------------------------------------------------------
// Kernel 2: fused GRU cell — R8 tile geometry (2 CTAs/SM) + cp.async 3-stage
// pipeline (1 syncthreads per chunk, loads 2 chunks ahead).
// CTA: 256 thr, 8 warps = 4m x 2n; CTA tile 128 rows x 32 j.
// Chunk c in 0..15: phase ph=c>>3 (0: A=h0/W=Whh -> ar,az,hn; 1: A=P/W=Wih -> ar,az,in)
// ---------------------------------------------------------------------------
#define AS_SZ  (128 * SMS)
#define WS_SZ  (96 * SMS)
#define STG_SZ (AS_SZ + WS_SZ)
#define GRU_SMEM_BYTES (3 * STG_SZ * 4)

__global__ __launch_bounds__(256, 2) void gru_kernel(
    const float* __restrict__ H0,
    const float* __restrict__ bih,
    const float* __restrict__ bhh,
    float* __restrict__ out)
{
    extern __shared__ unsigned smem[];
    unsigned sbase;
    asm("{ .reg .u64 t; cvta.to.shared.u64 t, %1; cvt.u32.u64 %0, t; }"
        : "=r"(sbase) : "l"(smem));

    const int tid  = threadIdx.x;
    const int lane = tid & 31;
    const int warp = tid >> 5;
    const int g    = lane >> 2;
    const int tg   = lane & 3;
    const int wm   = warp >> 1;   // 0..3 -> 32 rows each
    const int wn   = warp & 1;    // 0..1 -> 16 j each
    const int m0   = blockIdx.y * 128;
    const int j0   = blockIdx.x * 32;
    const int rbase = tid >> 3;        // 0..31
    const int c4    = (tid & 7) << 2;  // 0,4,..,28

    float ar[2][2][4], az[2][2][4], ain[2][2][4], ahn[2][2][4];
    #pragma unroll
    for (int i = 0; i < 2; i++)
        #pragma unroll
        for (int j = 0; j < 2; j++)
            #pragma unroll
            for (int q = 0; q < 4; q++) {
                ar[i][j][q] = 0.f; az[i][j][q] = 0.f;
                ain[i][j][q] = 0.f; ahn[i][j][q] = 0.f;
            }

    // issue chunk n (async copy into stage n%3, one commit group)
    auto issue = [&](int n) {
        int ph = n >> 3;
        int kc = (n & 7) * KCH;
        const float*    A = ph ? (const float*)g_P : H0;
        const unsigned* W = ph ? g_Wih_t : g_Whh_t;
        unsigned st = sbase + (unsigned)((n % 3) * STG_SZ) * 4u;
        #pragma unroll
        for (int i = 0; i < 4; i++) {
            int row = rbase + 32 * i;
            cpa16(st + (unsigned)(row * SMS + c4) * 4u,
                  &A[(size_t)(m0 + row) * HH + kc + c4]);
        }
        unsigned wst = st + (unsigned)AS_SZ * 4u;
        #pragma unroll
        for (int i = 0; i < 3; i++) {
            int row  = rbase + 32 * i;     // 0..95
            int gate = row >> 5;
            int jj   = row & 31;
            cpa16(wst + (unsigned)(row * SMS + c4) * 4u,
                  &W[(size_t)(gate * HH + j0 + jj) * HH + kc + c4]);
        }
        asm volatile("cp.async.commit_group;" ::: "memory");
    };

    issue(0);
    issue(1);

    #pragma unroll
    for (int ph = 0; ph < 2; ph++) {
        for (int kci = 0; kci < 8; kci++) {
            int c = ph * 8 + kci;
            if (c < 15) asm volatile("cp.async.wait_group 1;" ::: "memory");
            else        asm volatile("cp.async.wait_group 0;" ::: "memory");
            __syncthreads();   // chunk c landed; all warps done reading stage (c%3)'s prior occupant
            if (c + 2 < 16) issue(c + 2);

            const unsigned* As = smem + (c % 3) * STG_SZ;
            const unsigned* Ws = As + AS_SZ;

            #pragma unroll
            for (int ks = 0; ks < KCH; ks += 8) {
                unsigned a[2][4];
                #pragma unroll
                for (int fm = 0; fm < 2; fm++) {
                    int r = wm * 32 + fm * 16 + g;
                    const unsigned* base = &As[r * SMS + ks + tg];
                    a[fm][0] = base[0];
                    a[fm][1] = base[8 * SMS];
                    a[fm][2] = base[4];
                    a[fm][3] = base[8 * SMS + 4];
                }
                #pragma unroll
                for (int gate = 0; gate < 3; gate++) {
                    #pragma unroll
                    for (int fn = 0; fn < 2; fn++) {
                        int nr = gate * 32 + wn * 16 + fn * 8 + g;
                        unsigned b[2];
                        b[0] = Ws[nr * SMS + ks + tg];
                        b[1] = Ws[nr * SMS + ks + tg + 4];
                        #pragma unroll
                        for (int fm = 0; fm < 2; fm++) {
                            float* acc = (gate == 0) ? ar[fm][fn]
                                       : (gate == 1) ? az[fm][fn]
                                       : ((ph == 0) ? ahn[fm][fn] : ain[fm][fn]);
                            mma8(acc, a[fm], b);
                        }
                    }
                }
            }
            // no trailing sync: stage (c%3) is re-written at iter c+1's issue,
            // which is ordered after iter c+1's top-of-loop __syncthreads.
        }
    }

    // ---- Epilogue: biases, gates, blend, write both output copies ----
    const size_t BH = (size_t)BTOT * (size_t)HH;
    #pragma unroll
    for (int fm = 0; fm < 2; fm++) {
        #pragma unroll
        for (int fn = 0; fn < 2; fn++) {
            int rbas = m0 + wm * 32 + fm * 16 + g;
            int jb   = j0 + wn * 16 + fn * 8 + tg * 2;
            #pragma unroll
            for (int half = 0; half < 2; half++) {
                int row = rbas + half * 8;
                int q0  = half * 2;
                float2 h0v = *(const float2*)&H0[(size_t)row * HH + jb];
                float vr0 = ar[fm][fn][q0]      + bih[jb]              + bhh[jb];
                float vr1 = ar[fm][fn][q0 + 1]  + bih[jb + 1]          + bhh[jb + 1];
                float vz0 = az[fm][fn][q0]      + bih[HH + jb]         + bhh[HH + jb];
                float vz1 = az[fm][fn][q0 + 1]  + bih[HH + jb + 1]     + bhh[HH + jb + 1];
                float vi0 = ain[fm][fn][q0]     + bih[2 * HH + jb];
                float vi1 = ain[fm][fn][q0 + 1] + bih[2 * HH + jb + 1];
                float vh0 = ahn[fm][fn][q0]     + bhh[2 * HH + jb];
                float vh1 = ahn[fm][fn][q0 + 1] + bhh[2 * HH + jb + 1];
                float rr0 = 1.f / (1.f + __expf(-vr0));
                float rr1 = 1.f / (1.f + __expf(-vr1));
                float zz0 = 1.f / (1.f + __expf(-vz0));
                float zz1 = 1.f / (1.f + __expf(-vz1));
                float nn0 = tanhf(vi0 + rr0 * vh0);
                float nn1 = tanhf(vi1 + rr1 * vh1);
                float2 nh;
                nh.x = fmaf(zz0, h0v.x - nn0, nn0);
                nh.y = fmaf(zz1, h0v.y - nn1, nn1);
                size_t idx = (size_t)row * HH + jb;
                *(float2*)&out[idx]      = nh;
                *(float2*)&out[BH + idx] = nh;
            }
        }
    }
}

// ---------------------------------------------------------------------------
// kernel_launch: inputs in metadata order x, h, Wp, bp, W_ih, W_hh, b_ih, b_hh
// ---------------------------------------------------------------------------
extern "C" void kernel_launch(void* const* d_in, const int* in_sizes, int n_in,
                              void* d_out, int out_size) {
    const float* x   = (const float*)d_in[0];
    const float* h   = (const float*)d_in[1];   // (1, B, H) contiguous == (B, H)
    const float* Wp  = (const float*)d_in[2];
    const float* bp  = (const float*)d_in[3];
    const float* Wih = (const float*)d_in[4];
    const float* Whh = (const float*)d_in[5];
    const float* bih = (const float*)d_in[6];
    const float* bhh = (const float*)d_in[7];
    float* out = (float*)d_out;

    static bool attr_set = false;
    if (!attr_set) {
        cudaFuncSetAttribute(gru_kernel,
                             cudaFuncAttributeMaxDynamicSharedMemorySize,
                             GRU_SMEM_BYTES);
        attr_set = true;
    }

    wprep_kernel<<<768, 256>>>(Wih, Whh);

    dim3 gA(HH / 64, BTOT / 128);   // (4, 1024)
    proj_kernel<<<gA, 256>>>(x, Wp, bp);

    dim3 gB(HH / 32, BTOT / 128);   // (8, 1024) — j fastest for L2 reuse of h/P tiles
    gru_kernel<<<gB, 256, GRU_SMEM_BYTES>>>(h, bih, bhh, out);
}